// round 9
// baseline (speedup 1.0000x reference)
#include <cuda_runtime.h>
#include <stdint.h>

// RGINConv: out = feat + segment_sum_dst( feat[src] @ W[etype] )
//
// Restructured (GEMM-last):
//   1. CSR of edges grouped by dst (hist + hierarchical scan + scatter)
//   2. pull_agg: warp/node, H[r][n] = sum of feat[src] over incoming edges of
//      relation r. Gathers hit feat (25.6MB, L2-resident); H written streaming.
//   3. Fused grouped GEMM: out = feat + sum_r H_r @ W[r]  (tf32 mma, K=1024)

#define DFEAT 128
#define MAX_N 50048
#define MAX_E 640000
#define MAX_R 8
#define SCAN_CHUNK 1024
#define MAX_NB ((MAX_N + SCAN_CHUNK - 1) / SCAN_CHUNK)

__device__ float    g_H[(size_t)MAX_R * MAX_N * DFEAT];  // ~205 MB scratch
__device__ int      g_rowptr[MAX_N + 1];
__device__ int      g_cursor[MAX_N];
__device__ int      g_deg[MAX_N];
__device__ int      g_bsum[MAX_NB];
__device__ unsigned g_elist[MAX_E];   // (src << 3) | etype

// ---------------------------------------------------------------------------
// CSR build
// ---------------------------------------------------------------------------
__global__ void zero_deg_k(int n)
{
    int i = blockIdx.x * blockDim.x + threadIdx.x;
    if (i < n) g_deg[i] = 0;
}

__global__ void hist_k(const int* __restrict__ dst, int E)
{
    int e = blockIdx.x * blockDim.x + threadIdx.x;
    if (e < E) atomicAdd(&g_deg[dst[e]], 1);
}

// Scan stage 1: each CTA (256 thr) scans SCAN_CHUNK=1024 degrees locally.
__global__ void scan1_k(int n)
{
    const int tid  = threadIdx.x;
    const int blk  = blockIdx.x;
    const int base = blk * SCAN_CHUNK + tid * 4;

    int d0 = 0, d1 = 0, d2 = 0, d3 = 0;
    if (base     < n) d0 = g_deg[base];
    if (base + 1 < n) d1 = g_deg[base + 1];
    if (base + 2 < n) d2 = g_deg[base + 2];
    if (base + 3 < n) d3 = g_deg[base + 3];
    int s = d0 + d1 + d2 + d3;

    const int lane = tid & 31, wid = tid >> 5;
    int v = s;
#pragma unroll
    for (int off = 1; off < 32; off <<= 1) {
        int t = __shfl_up_sync(0xffffffffu, v, off);
        if (lane >= off) v += t;
    }
    __shared__ int ws[8];
    if (lane == 31) ws[wid] = v;
    __syncthreads();
    if (tid == 0) {
        int r = 0;
#pragma unroll
        for (int i = 0; i < 8; ++i) { int t = ws[i]; ws[i] = r; r += t; }
    }
    __syncthreads();

    int excl = (v - s) + ws[wid];
    if (tid == 255) g_bsum[blk] = excl + s;

    if (base     < n) g_rowptr[base]     = excl;           excl += d0;
    if (base + 1 < n) g_rowptr[base + 1] = excl;           excl += d1;
    if (base + 2 < n) g_rowptr[base + 2] = excl;           excl += d2;
    if (base + 3 < n) g_rowptr[base + 3] = excl;
}

// Scan stage 2: one warp exclusive-scans the <=64 block sums.
__global__ void scan2_k(int nb)
{
    const int lane = threadIdx.x;
    int i0 = lane * 2, i1 = lane * 2 + 1;
    int a = (i0 < nb) ? g_bsum[i0] : 0;
    int b = (i1 < nb) ? g_bsum[i1] : 0;
    int s = a + b, v = s;
#pragma unroll
    for (int off = 1; off < 32; off <<= 1) {
        int t = __shfl_up_sync(0xffffffffu, v, off);
        if (lane >= off) v += t;
    }
    int excl = v - s;
    if (i0 < nb) g_bsum[i0] = excl;
    if (i1 < nb) g_bsum[i1] = excl + a;
}

// Scan stage 3: add block offsets, materialize rowptr + cursor.
__global__ void scan3_k(int n, int E)
{
    const int tid  = threadIdx.x;
    const int blk  = blockIdx.x;
    const int off  = g_bsum[blk];
    const int base = blk * SCAN_CHUNK + tid * 4;
#pragma unroll
    for (int j = 0; j < 4; ++j) {
        int idx = base + j;
        if (idx < n) {
            int r = g_rowptr[idx] + off;
            g_rowptr[idx] = r;
            g_cursor[idx] = r;
        }
    }
    if (blk == 0 && tid == 0) g_rowptr[n] = E;
}

__global__ void scatter_k(const int* __restrict__ src, const int* __restrict__ dst,
                          const int* __restrict__ et, int E)
{
    int e = blockIdx.x * blockDim.x + threadIdx.x;
    if (e >= E) return;
    int d   = dst[e];
    int pos = atomicAdd(&g_cursor[d], 1);
    g_elist[pos] = ((unsigned)src[e] << 3) | (unsigned)et[e];
}

// ---------------------------------------------------------------------------
// pull_agg: one warp per node. 8 per-relation float4 accumulators per lane.
// etype is warp-uniform per edge -> uniform switch, no divergence/spill.
// ---------------------------------------------------------------------------
#define ACC_ADD(ET, V)                                                        \
    switch (ET) {                                                             \
    case 0: a0.x += V.x; a0.y += V.y; a0.z += V.z; a0.w += V.w; break;        \
    case 1: a1.x += V.x; a1.y += V.y; a1.z += V.z; a1.w += V.w; break;        \
    case 2: a2.x += V.x; a2.y += V.y; a2.z += V.z; a2.w += V.w; break;        \
    case 3: a3.x += V.x; a3.y += V.y; a3.z += V.z; a3.w += V.w; break;        \
    case 4: a4.x += V.x; a4.y += V.y; a4.z += V.z; a4.w += V.w; break;        \
    case 5: a5.x += V.x; a5.y += V.y; a5.z += V.z; a5.w += V.w; break;        \
    case 6: a6.x += V.x; a6.y += V.y; a6.z += V.z; a6.w += V.w; break;        \
    default: a7.x += V.x; a7.y += V.y; a7.z += V.z; a7.w += V.w; break;       \
    }

__global__ void __launch_bounds__(256)
pull_agg(const float* __restrict__ feat, int n)
{
    int gw   = (blockIdx.x * 256 + threadIdx.x) >> 5;
    int lane = threadIdx.x & 31;
    if (gw >= n) return;

    int s = g_rowptr[gw];
    int e = g_rowptr[gw + 1];

    const float4* f4 = (const float4*)feat;
    float4 a0 = make_float4(0.f, 0.f, 0.f, 0.f), a1 = a0, a2 = a0, a3 = a0,
           a4 = a0, a5 = a0, a6 = a0, a7 = a0;

    int i = s;
    for (; i + 4 <= e; i += 4) {
        unsigned o0 = g_elist[i];
        unsigned o1 = g_elist[i + 1];
        unsigned o2 = g_elist[i + 2];
        unsigned o3 = g_elist[i + 3];
        float4 v0 = f4[(size_t)(o0 >> 3) * 32 + lane];
        float4 v1 = f4[(size_t)(o1 >> 3) * 32 + lane];
        float4 v2 = f4[(size_t)(o2 >> 3) * 32 + lane];
        float4 v3 = f4[(size_t)(o3 >> 3) * 32 + lane];
        ACC_ADD(o0 & 7, v0)
        ACC_ADD(o1 & 7, v1)
        ACC_ADD(o2 & 7, v2)
        ACC_ADD(o3 & 7, v3)
    }
    for (; i < e; ++i) {
        unsigned o = g_elist[i];
        float4 v = f4[(size_t)(o >> 3) * 32 + lane];
        ACC_ADD(o & 7, v)
    }

    // Write all 8 relation rows (zeros included -> no separate H clear).
    size_t stride = (size_t)n * 32;            // float4 per relation plane
    float4* h4 = (float4*)g_H + (size_t)gw * 32 + lane;
    h4[0]          = a0;
    h4[stride]     = a1;
    h4[stride * 2] = a2;
    h4[stride * 3] = a3;
    h4[stride * 4] = a4;
    h4[stride * 5] = a5;
    h4[stride * 6] = a6;
    h4[stride * 7] = a7;
}

// ---------------------------------------------------------------------------
// Fused grouped GEMM: out = feat + sum_r H_r @ W[r].
// CTA tile 128(M) x 128(N); 8 warps, warp tile 32(M) x 64(N); tf32 mma.
// K loop = 8 relations x 128.
// ---------------------------------------------------------------------------
#define CTM 128
#define GLD 132   // padded smem row stride (words)

__global__ void __launch_bounds__(256, 1)
gemm_out(const float* __restrict__ feat, const float* __restrict__ W,
         float* __restrict__ out, int n)
{
    extern __shared__ unsigned sh[];
    unsigned* As = sh;                  // [128][GLD]
    unsigned* Bs = sh + CTM * GLD;      // [128][GLD]

    const int row0 = blockIdx.x * CTM;
    const int tid  = threadIdx.x;
    const int wid  = tid >> 5;
    const int lane = tid & 31;
    const int g    = lane >> 2;    // 0..7
    const int c    = lane & 3;     // 0..3
    const int wm   = wid >> 1;     // 0..3 : rows wm*32
    const int wn   = wid & 1;      // 0..1 : cols wn*64

    float acc[2][8][4];
#pragma unroll
    for (int mt = 0; mt < 2; ++mt)
#pragma unroll
        for (int nt = 0; nt < 8; ++nt)
#pragma unroll
            for (int i = 0; i < 4; ++i) acc[mt][nt][i] = 0.f;

    for (int rel = 0; rel < MAX_R; ++rel) {
        __syncthreads();   // previous iteration's compute done before reload

        const float* Hr = g_H + (size_t)rel * n * DFEAT;
        // A tile: 128x128 floats -> 16 float4 per thread
#pragma unroll
        for (int it = 0; it < 16; ++it) {
            int idx = it * 256 + tid;
            int r   = idx >> 5;
            int col = (idx & 31) * 4;
            float4 v = make_float4(0.f, 0.f, 0.f, 0.f);
            int gr = row0 + r;
            if (gr < n) v = *(const float4*)(Hr + (size_t)gr * DFEAT + col);
            unsigned* p = As + r * GLD + col;
            asm("cvt.rna.tf32.f32 %0, %1;" : "=r"(p[0]) : "f"(v.x));
            asm("cvt.rna.tf32.f32 %0, %1;" : "=r"(p[1]) : "f"(v.y));
            asm("cvt.rna.tf32.f32 %0, %1;" : "=r"(p[2]) : "f"(v.z));
            asm("cvt.rna.tf32.f32 %0, %1;" : "=r"(p[3]) : "f"(v.w));
        }
        const float* Wr = W + (size_t)rel * DFEAT * DFEAT;
#pragma unroll
        for (int it = 0; it < 16; ++it) {
            int idx = it * 256 + tid;
            int r   = idx >> 5;
            int col = (idx & 31) * 4;
            float4 v = *(const float4*)(Wr + r * DFEAT + col);
            unsigned* p = Bs + r * GLD + col;
            asm("cvt.rna.tf32.f32 %0, %1;" : "=r"(p[0]) : "f"(v.x));
            asm("cvt.rna.tf32.f32 %0, %1;" : "=r"(p[1]) : "f"(v.y));
            asm("cvt.rna.tf32.f32 %0, %1;" : "=r"(p[2]) : "f"(v.z));
            asm("cvt.rna.tf32.f32 %0, %1;" : "=r"(p[3]) : "f"(v.w));
        }
        __syncthreads();

#pragma unroll
        for (int k0 = 0; k0 < DFEAT; k0 += 8) {
            unsigned a[2][4], b[8][2];
#pragma unroll
            for (int mt = 0; mt < 2; ++mt) {
                int rb = wm * 32 + mt * 16;
                a[mt][0] = As[(rb + g)     * GLD + k0 + c];
                a[mt][1] = As[(rb + g + 8) * GLD + k0 + c];
                a[mt][2] = As[(rb + g)     * GLD + k0 + c + 4];
                a[mt][3] = As[(rb + g + 8) * GLD + k0 + c + 4];
            }
#pragma unroll
            for (int nt = 0; nt < 8; ++nt) {
                int nb = wn * 64 + nt * 8;
                b[nt][0] = Bs[(k0 + c)     * GLD + nb + g];
                b[nt][1] = Bs[(k0 + c + 4) * GLD + nb + g];
            }
#pragma unroll
            for (int mt = 0; mt < 2; ++mt)
#pragma unroll
                for (int nt = 0; nt < 8; ++nt)
                    asm volatile(
                        "mma.sync.aligned.m16n8k8.row.col.f32.tf32.tf32.f32 "
                        "{%0,%1,%2,%3}, {%4,%5,%6,%7}, {%8,%9}, {%0,%1,%2,%3};"
                        : "+f"(acc[mt][nt][0]), "+f"(acc[mt][nt][1]),
                          "+f"(acc[mt][nt][2]), "+f"(acc[mt][nt][3])
                        : "r"(a[mt][0]), "r"(a[mt][1]), "r"(a[mt][2]), "r"(a[mt][3]),
                          "r"(b[nt][0]), "r"(b[nt][1]));
        }
    }

    // Epilogue: out = feat + acc
#pragma unroll
    for (int mt = 0; mt < 2; ++mt) {
        int r_lo = row0 + wm * 32 + mt * 16 + g;
        int r_hi = r_lo + 8;
#pragma unroll
        for (int nt = 0; nt < 8; ++nt) {
            int col = wn * 64 + nt * 8 + 2 * c;
            if (r_lo < n) {
                float2 f = *(const float2*)(feat + (size_t)r_lo * DFEAT + col);
                *(float2*)(out + (size_t)r_lo * DFEAT + col) =
                    make_float2(f.x + acc[mt][nt][0], f.y + acc[mt][nt][1]);
            }
            if (r_hi < n) {
                float2 f = *(const float2*)(feat + (size_t)r_hi * DFEAT + col);
                *(float2*)(out + (size_t)r_hi * DFEAT + col) =
                    make_float2(f.x + acc[mt][nt][2], f.y + acc[mt][nt][3]);
            }
        }
    }
}

// ---------------------------------------------------------------------------
// Launch
// ---------------------------------------------------------------------------
extern "C" void kernel_launch(void* const* d_in, const int* in_sizes, int n_in,
                              void* d_out, int out_size)
{
    const float* feat = (const float*)d_in[0];
    const float* W    = (const float*)d_in[1];
    const int*   et   = (const int*)d_in[2];
    const int*   src  = (const int*)d_in[3];
    const int*   dst  = (const int*)d_in[4];
    float*       out  = (float*)d_out;

    const int n  = in_sizes[0] / DFEAT;                 // 50000
    const int E  = in_sizes[2];                          // 640000
    const int nb = (n + SCAN_CHUNK - 1) / SCAN_CHUNK;    // 49

    zero_deg_k<<<(n + 255) / 256, 256>>>(n);
    hist_k<<<(E + 255) / 256, 256>>>(dst, E);
    scan1_k<<<nb, 256>>>(n);
    scan2_k<<<1, 32>>>(nb);
    scan3_k<<<nb, 256>>>(n, E);
    scatter_k<<<(E + 255) / 256, 256>>>(src, dst, et, E);

    pull_agg<<<(n * 32 + 255) / 256, 256>>>(feat, n);

    const int smem_bytes = 2 * CTM * GLD * 4;   // ~132 KB
    cudaFuncSetAttribute(gemm_out,
                         cudaFuncAttributeMaxDynamicSharedMemorySize, smem_bytes);
    gemm_out<<<(n + CTM - 1) / CTM, 256, smem_bytes>>>(feat, W, out, n);
}

// round 10
// speedup vs baseline: 1.2764x; 1.2764x over previous
#include <cuda_runtime.h>
#include <cuda_fp16.h>
#include <stdint.h>

// RGINConv: out = feat + segment_sum_dst( feat[src] @ W[etype] )
//
// GEMM-first (measured-best structure), Y stored in fp16 (halves Y traffic,
// makes Y L2-resident: 102MB < 126MB L2):
//   1. Y[r] = feat @ W[r]  (8 GEMMs, tf32 mma, fp32 accum, fp16 store)
//   2. CSR of edges grouped by dst (hist + hierarchical scan + scatter)
//   3. Pull: warp per node, acc(fp32) = feat[n] + sum of fp16 Y rows

#define DFEAT 128
#define MAX_N 50048
#define MAX_E 640000
#define MAX_R 8
#define SCAN_CHUNK 1024
#define MAX_NB ((MAX_N + SCAN_CHUNK - 1) / SCAN_CHUNK)

__device__ __half    g_Y[(size_t)MAX_R * MAX_N * DFEAT];  // ~102 MB scratch
__device__ int       g_rowptr[MAX_N + 1];
__device__ int       g_cursor[MAX_N];
__device__ int       g_deg[MAX_N];
__device__ int       g_bsum[MAX_NB];
__device__ unsigned  g_elist[MAX_E];   // half-offset of Y row for this edge

// ---------------------------------------------------------------------------
// GEMM: Y[rel] = feat @ W[rel],  tf32 mma, fp16 output.
// CTA tile: 64(M) x 128(N); 8 warps in 2(M) x 4(N) grid, warp tile 32x32.
// ---------------------------------------------------------------------------
#define TM 64
#define AS_LD 132   // padded A smem row stride (words)
#define BS_LD 136   // padded B smem row stride (words)

__global__ void __launch_bounds__(256, 2)
gemm_feat_w(const float* __restrict__ feat, const float* __restrict__ W, int n_nodes)
{
    extern __shared__ unsigned sh[];
    unsigned* As = sh;                    // [TM][AS_LD]
    unsigned* Bs = sh + TM * AS_LD;       // [128][BS_LD]

    const int rel  = blockIdx.y;
    const int row0 = blockIdx.x * TM;
    const int tid  = threadIdx.x;

#pragma unroll
    for (int it = 0; it < (TM * DFEAT) / (256 * 4); ++it) {
        int idx = it * 256 + tid;           // float4 index
        int r   = idx >> 5;                 // 32 float4 per row
        int c   = (idx & 31) * 4;
        float4 v = make_float4(0.f, 0.f, 0.f, 0.f);
        int gr = row0 + r;
        if (gr < n_nodes) v = *(const float4*)(feat + (size_t)gr * DFEAT + c);
        unsigned* p = As + r * AS_LD + c;
        asm("cvt.rna.tf32.f32 %0, %1;" : "=r"(p[0]) : "f"(v.x));
        asm("cvt.rna.tf32.f32 %0, %1;" : "=r"(p[1]) : "f"(v.y));
        asm("cvt.rna.tf32.f32 %0, %1;" : "=r"(p[2]) : "f"(v.z));
        asm("cvt.rna.tf32.f32 %0, %1;" : "=r"(p[3]) : "f"(v.w));
    }
    const float* Wr = W + (size_t)rel * DFEAT * DFEAT;
#pragma unroll
    for (int it = 0; it < (DFEAT * DFEAT) / (256 * 4); ++it) {
        int idx = it * 256 + tid;
        int r   = idx >> 5;
        int c   = (idx & 31) * 4;
        float4 v = *(const float4*)(Wr + r * DFEAT + c);
        unsigned* p = Bs + r * BS_LD + c;
        asm("cvt.rna.tf32.f32 %0, %1;" : "=r"(p[0]) : "f"(v.x));
        asm("cvt.rna.tf32.f32 %0, %1;" : "=r"(p[1]) : "f"(v.y));
        asm("cvt.rna.tf32.f32 %0, %1;" : "=r"(p[2]) : "f"(v.z));
        asm("cvt.rna.tf32.f32 %0, %1;" : "=r"(p[3]) : "f"(v.w));
    }
    __syncthreads();

    const int wid  = tid >> 5;
    const int lane = tid & 31;
    const int g    = lane >> 2;   // 0..7
    const int c    = lane & 3;    // 0..3
    const int wm   = wid & 1;     // warp M index
    const int wn   = wid >> 1;    // warp N index

    float acc[2][4][4];
#pragma unroll
    for (int mt = 0; mt < 2; ++mt)
#pragma unroll
        for (int nt = 0; nt < 4; ++nt)
#pragma unroll
            for (int i = 0; i < 4; ++i) acc[mt][nt][i] = 0.f;

#pragma unroll
    for (int k0 = 0; k0 < DFEAT; k0 += 8) {
        unsigned a[2][4], b[4][2];
#pragma unroll
        for (int mt = 0; mt < 2; ++mt) {
            int rb = wm * 32 + mt * 16;
            a[mt][0] = As[(rb + g)     * AS_LD + k0 + c];
            a[mt][1] = As[(rb + g + 8) * AS_LD + k0 + c];
            a[mt][2] = As[(rb + g)     * AS_LD + k0 + c + 4];
            a[mt][3] = As[(rb + g + 8) * AS_LD + k0 + c + 4];
        }
#pragma unroll
        for (int nt = 0; nt < 4; ++nt) {
            int nb = wn * 32 + nt * 8;
            b[nt][0] = Bs[(k0 + c)     * BS_LD + nb + g];
            b[nt][1] = Bs[(k0 + c + 4) * BS_LD + nb + g];
        }
#pragma unroll
        for (int mt = 0; mt < 2; ++mt)
#pragma unroll
            for (int nt = 0; nt < 4; ++nt)
                asm volatile(
                    "mma.sync.aligned.m16n8k8.row.col.f32.tf32.tf32.f32 "
                    "{%0,%1,%2,%3}, {%4,%5,%6,%7}, {%8,%9}, {%0,%1,%2,%3};"
                    : "+f"(acc[mt][nt][0]), "+f"(acc[mt][nt][1]),
                      "+f"(acc[mt][nt][2]), "+f"(acc[mt][nt][3])
                    : "r"(a[mt][0]), "r"(a[mt][1]), "r"(a[mt][2]), "r"(a[mt][3]),
                      "r"(b[nt][0]), "r"(b[nt][1]));
    }

    // Store D as fp16. c0,c1 at (row g, cols 2c,2c+1); c2,c3 at row g+8.
    __half* Yr = g_Y + (size_t)rel * n_nodes * DFEAT;
#pragma unroll
    for (int mt = 0; mt < 2; ++mt) {
        int r_lo = row0 + wm * 32 + mt * 16 + g;
        int r_hi = r_lo + 8;
#pragma unroll
        for (int nt = 0; nt < 4; ++nt) {
            int col = wn * 32 + nt * 8 + 2 * c;
            if (r_lo < n_nodes)
                *(__half2*)(Yr + (size_t)r_lo * DFEAT + col) =
                    __floats2half2_rn(acc[mt][nt][0], acc[mt][nt][1]);
            if (r_hi < n_nodes)
                *(__half2*)(Yr + (size_t)r_hi * DFEAT + col) =
                    __floats2half2_rn(acc[mt][nt][2], acc[mt][nt][3]);
        }
    }
}

// ---------------------------------------------------------------------------
// CSR build
// ---------------------------------------------------------------------------
__global__ void zero_deg_k(int n)
{
    int i = blockIdx.x * blockDim.x + threadIdx.x;
    if (i < n) g_deg[i] = 0;
}

__global__ void hist_k(const int* __restrict__ dst, int E)
{
    int e = blockIdx.x * blockDim.x + threadIdx.x;
    if (e < E) atomicAdd(&g_deg[dst[e]], 1);
}

__global__ void scan1_k(int n)
{
    const int tid  = threadIdx.x;
    const int blk  = blockIdx.x;
    const int base = blk * SCAN_CHUNK + tid * 4;

    int d0 = 0, d1 = 0, d2 = 0, d3 = 0;
    if (base     < n) d0 = g_deg[base];
    if (base + 1 < n) d1 = g_deg[base + 1];
    if (base + 2 < n) d2 = g_deg[base + 2];
    if (base + 3 < n) d3 = g_deg[base + 3];
    int s = d0 + d1 + d2 + d3;

    const int lane = tid & 31, wid = tid >> 5;
    int v = s;
#pragma unroll
    for (int off = 1; off < 32; off <<= 1) {
        int t = __shfl_up_sync(0xffffffffu, v, off);
        if (lane >= off) v += t;
    }
    __shared__ int ws[8];
    if (lane == 31) ws[wid] = v;
    __syncthreads();
    if (tid == 0) {
        int r = 0;
#pragma unroll
        for (int i = 0; i < 8; ++i) { int t = ws[i]; ws[i] = r; r += t; }
    }
    __syncthreads();

    int excl = (v - s) + ws[wid];
    if (tid == 255) g_bsum[blk] = excl + s;

    if (base     < n) g_rowptr[base]     = excl;           excl += d0;
    if (base + 1 < n) g_rowptr[base + 1] = excl;           excl += d1;
    if (base + 2 < n) g_rowptr[base + 2] = excl;           excl += d2;
    if (base + 3 < n) g_rowptr[base + 3] = excl;
}

__global__ void scan2_k(int nb)
{
    const int lane = threadIdx.x;
    int i0 = lane * 2, i1 = lane * 2 + 1;
    int a = (i0 < nb) ? g_bsum[i0] : 0;
    int b = (i1 < nb) ? g_bsum[i1] : 0;
    int s = a + b, v = s;
#pragma unroll
    for (int off = 1; off < 32; off <<= 1) {
        int t = __shfl_up_sync(0xffffffffu, v, off);
        if (lane >= off) v += t;
    }
    int excl = v - s;
    if (i0 < nb) g_bsum[i0] = excl;
    if (i1 < nb) g_bsum[i1] = excl + a;
}

__global__ void scan3_k(int n, int E)
{
    const int tid  = threadIdx.x;
    const int blk  = blockIdx.x;
    const int off  = g_bsum[blk];
    const int base = blk * SCAN_CHUNK + tid * 4;
#pragma unroll
    for (int j = 0; j < 4; ++j) {
        int idx = base + j;
        if (idx < n) {
            int r = g_rowptr[idx] + off;
            g_rowptr[idx] = r;
            g_cursor[idx] = r;
        }
    }
    if (blk == 0 && tid == 0) g_rowptr[n] = E;
}

__global__ void scatter_k(const int* __restrict__ src, const int* __restrict__ dst,
                          const int* __restrict__ et, int E, int n)
{
    int e = blockIdx.x * blockDim.x + threadIdx.x;
    if (e >= E) return;
    int d   = dst[e];
    int pos = atomicAdd(&g_cursor[d], 1);
    g_elist[pos] = ((unsigned)et[e] * (unsigned)n + (unsigned)src[e]) * (unsigned)DFEAT;
}

// ---------------------------------------------------------------------------
// Pull: one warp per node. acc(fp32) = feat[n] + sum of fp16 Y rows.
// Per edge per lane: one 8B load (4 halves). Unroll x4 for MLP.
// ---------------------------------------------------------------------------
__device__ __forceinline__ void acc_half4(float4& acc, uint2 u)
{
    float2 f0 = __half22float2(*(__half2*)&u.x);
    float2 f1 = __half22float2(*(__half2*)&u.y);
    acc.x += f0.x; acc.y += f0.y; acc.z += f1.x; acc.w += f1.y;
}

__global__ void __launch_bounds__(256)
pull_k(const float* __restrict__ feat, float* __restrict__ out, int n)
{
    int gw   = (blockIdx.x * 256 + threadIdx.x) >> 5;
    int lane = threadIdx.x & 31;
    if (gw >= n) return;

    int s = g_rowptr[gw];
    int e = g_rowptr[gw + 1];

    float4 acc = *((const float4*)feat + (size_t)gw * 32 + lane);
    const unsigned lo = (unsigned)lane * 4;   // half offset within row

    int i = s;
    for (; i + 4 <= e; i += 4) {
        unsigned o0 = g_elist[i];
        unsigned o1 = g_elist[i + 1];
        unsigned o2 = g_elist[i + 2];
        unsigned o3 = g_elist[i + 3];
        uint2 u0 = *(const uint2*)(g_Y + (size_t)o0 + lo);
        uint2 u1 = *(const uint2*)(g_Y + (size_t)o1 + lo);
        uint2 u2 = *(const uint2*)(g_Y + (size_t)o2 + lo);
        uint2 u3 = *(const uint2*)(g_Y + (size_t)o3 + lo);
        acc_half4(acc, u0);
        acc_half4(acc, u1);
        acc_half4(acc, u2);
        acc_half4(acc, u3);
    }
    for (; i < e; ++i) {
        unsigned o = g_elist[i];
        uint2 u = *(const uint2*)(g_Y + (size_t)o + lo);
        acc_half4(acc, u);
    }

    *((float4*)out + (size_t)gw * 32 + lane) = acc;
}

// ---------------------------------------------------------------------------
// Launch
// ---------------------------------------------------------------------------
extern "C" void kernel_launch(void* const* d_in, const int* in_sizes, int n_in,
                              void* d_out, int out_size)
{
    const float* feat = (const float*)d_in[0];
    const float* W    = (const float*)d_in[1];
    const int*   et   = (const int*)d_in[2];
    const int*   src  = (const int*)d_in[3];
    const int*   dst  = (const int*)d_in[4];
    float*       out  = (float*)d_out;

    const int n  = in_sizes[0] / DFEAT;                 // 50000
    const int R  = in_sizes[1] / (DFEAT * DFEAT);       // 8
    const int E  = in_sizes[2];                          // 640000
    const int nb = (n + SCAN_CHUNK - 1) / SCAN_CHUNK;    // 49

    const int smem_bytes = (TM * AS_LD + DFEAT * BS_LD) * 4;  // ~103 KB
    cudaFuncSetAttribute(gemm_feat_w,
                         cudaFuncAttributeMaxDynamicSharedMemorySize, smem_bytes);

    dim3 gg((n + TM - 1) / TM, R);
    gemm_feat_w<<<gg, 256, smem_bytes>>>(feat, W, n);

    zero_deg_k<<<(n + 255) / 256, 256>>>(n);
    hist_k<<<(E + 255) / 256, 256>>>(dst, E);
    scan1_k<<<nb, 256>>>(n);
    scan2_k<<<1, 32>>>(nb);
    scan3_k<<<nb, 256>>>(n, E);
    scatter_k<<<(E + 255) / 256, 256>>>(src, dst, et, E, n);

    pull_k<<<(n * 32 + 255) / 256, 256>>>(feat, out, n);
}

// round 11
// speedup vs baseline: 1.7448x; 1.3669x over previous
#include <cuda_runtime.h>
#include <cuda_fp16.h>
#include <stdint.h>

// RGINConv: out = feat + segment_sum_dst( feat[src] @ W[etype] )
//
// GEMM-first, fp16 end-to-end in the middle:
//   0. Wt[r][n][k] = fp16 transpose of W  (tiny, one kernel)
//   1. Y[r] = feat @ W[r]  (fp16 mma m16n8k16, fp32 accum, fp16 store)
//   2. CSR of edges grouped by dst (hist + hierarchical scan + scatter)
//   3. Pull: warp per node, acc(fp32) = feat[n] + sum of fp16 Y rows

#define DFEAT 128
#define MAX_N 50048
#define MAX_E 640000
#define MAX_R 8
#define SCAN_CHUNK 1024
#define MAX_NB ((MAX_N + SCAN_CHUNK - 1) / SCAN_CHUNK)

__device__ __half    g_Y[(size_t)MAX_R * MAX_N * DFEAT];  // ~102 MB scratch
__device__ __half    g_Wt[MAX_R * DFEAT * DFEAT];         // W transposed, fp16
__device__ int       g_rowptr[MAX_N + 1];
__device__ int       g_cursor[MAX_N];
__device__ int       g_deg[MAX_N];
__device__ int       g_bsum[MAX_NB];
__device__ unsigned  g_elist[MAX_E];   // half-offset of Y row for this edge

// ---------------------------------------------------------------------------
// W transpose: Wt[r][n][k] = (half)W[r][k][n].  grid (4,4,R), block (32,8).
// ---------------------------------------------------------------------------
__global__ void transpose_w(const float* __restrict__ W)
{
    __shared__ float t[32][33];
    const int r  = blockIdx.z;
    const int k0 = blockIdx.x * 32;
    const int n0 = blockIdx.y * 32;
    const float* Wr = W + (size_t)r * DFEAT * DFEAT;
#pragma unroll
    for (int j = 0; j < 4; ++j)
        t[threadIdx.y + j * 8][threadIdx.x] =
            Wr[(size_t)(k0 + threadIdx.y + j * 8) * DFEAT + n0 + threadIdx.x];
    __syncthreads();
    __half* Wt = g_Wt + (size_t)r * DFEAT * DFEAT;
#pragma unroll
    for (int j = 0; j < 4; ++j)
        Wt[(size_t)(n0 + threadIdx.y + j * 8) * DFEAT + k0 + threadIdx.x] =
            __float2half(t[threadIdx.x][threadIdx.y + j * 8]);
}

// ---------------------------------------------------------------------------
// GEMM: Y[rel] = feat @ W[rel],  fp16 mma m16n8k16, fp32 accum, fp16 store.
// CTA tile: 64(M) x 128(N); 8 warps in 2(M) x 4(N) grid, warp tile 32x32.
// Smem in halves, LD=136 -> fragment LDS conflict-free (word = 4g+c mod 32).
// ---------------------------------------------------------------------------
#define TM 64
#define HLD 136   // smem row stride in halves (both tiles)

__global__ void __launch_bounds__(256, 2)
gemm_feat_w(const float* __restrict__ feat, int n_nodes)
{
    extern __shared__ __half sh[];
    __half* As = sh;                 // [TM][HLD]
    __half* Bs = sh + TM * HLD;      // [128][HLD]   (Wt rows: n-major, k-contig)

    const int rel  = blockIdx.y;
    const int row0 = blockIdx.x * TM;
    const int tid  = threadIdx.x;

    // A tile: 64x128 floats -> fp16. 8 float4 per thread.
#pragma unroll
    for (int it = 0; it < (TM * DFEAT) / (256 * 4); ++it) {
        int idx = it * 256 + tid;
        int r   = idx >> 5;
        int c   = (idx & 31) * 4;
        float4 v = make_float4(0.f, 0.f, 0.f, 0.f);
        int gr = row0 + r;
        if (gr < n_nodes) v = *(const float4*)(feat + (size_t)gr * DFEAT + c);
        __half2* p = (__half2*)(As + r * HLD + c);
        p[0] = __floats2half2_rn(v.x, v.y);
        p[1] = __floats2half2_rn(v.z, v.w);
    }
    // B tile: Wt[rel] 128x128 halves, 16B vector copies. 8 per thread.
    const float4* Wt4 = (const float4*)(g_Wt + (size_t)rel * DFEAT * DFEAT);
#pragma unroll
    for (int it = 0; it < (DFEAT * DFEAT) / (256 * 8); ++it) {
        int idx  = it * 256 + tid;      // 16-byte chunk index (8 halves)
        int nrow = idx >> 4;            // 16 chunks per 128-half row
        int koff = (idx & 15) * 8;
        *(float4*)(Bs + nrow * HLD + koff) = Wt4[idx];
    }
    __syncthreads();

    const int wid  = tid >> 5;
    const int lane = tid & 31;
    const int g    = lane >> 2;   // 0..7
    const int c    = lane & 3;    // 0..3
    const int wm   = wid & 1;     // warp M index (rows wm*32)
    const int wn   = wid >> 1;    // warp N index (cols wn*32)

    float acc[2][4][4];
#pragma unroll
    for (int mt = 0; mt < 2; ++mt)
#pragma unroll
        for (int nt = 0; nt < 4; ++nt)
#pragma unroll
            for (int i = 0; i < 4; ++i) acc[mt][nt][i] = 0.f;

#pragma unroll
    for (int k0 = 0; k0 < DFEAT; k0 += 16) {
        unsigned a[2][4], b[4][2];
#pragma unroll
        for (int mt = 0; mt < 2; ++mt) {
            int rb = wm * 32 + mt * 16;
            a[mt][0] = *(const unsigned*)(As + (rb + g)     * HLD + k0 + 2 * c);
            a[mt][1] = *(const unsigned*)(As + (rb + g + 8) * HLD + k0 + 2 * c);
            a[mt][2] = *(const unsigned*)(As + (rb + g)     * HLD + k0 + 2 * c + 8);
            a[mt][3] = *(const unsigned*)(As + (rb + g + 8) * HLD + k0 + 2 * c + 8);
        }
#pragma unroll
        for (int nt = 0; nt < 4; ++nt) {
            int nb = wn * 32 + nt * 8;
            b[nt][0] = *(const unsigned*)(Bs + (nb + g) * HLD + k0 + 2 * c);
            b[nt][1] = *(const unsigned*)(Bs + (nb + g) * HLD + k0 + 2 * c + 8);
        }
#pragma unroll
        for (int mt = 0; mt < 2; ++mt)
#pragma unroll
            for (int nt = 0; nt < 4; ++nt)
                asm volatile(
                    "mma.sync.aligned.m16n8k16.row.col.f32.f16.f16.f32 "
                    "{%0,%1,%2,%3}, {%4,%5,%6,%7}, {%8,%9}, {%0,%1,%2,%3};"
                    : "+f"(acc[mt][nt][0]), "+f"(acc[mt][nt][1]),
                      "+f"(acc[mt][nt][2]), "+f"(acc[mt][nt][3])
                    : "r"(a[mt][0]), "r"(a[mt][1]), "r"(a[mt][2]), "r"(a[mt][3]),
                      "r"(b[nt][0]), "r"(b[nt][1]));
    }

    // Store D as fp16. c0,c1 at (row g, cols 2c,2c+1); c2,c3 at row g+8.
    __half* Yr = g_Y + (size_t)rel * n_nodes * DFEAT;
#pragma unroll
    for (int mt = 0; mt < 2; ++mt) {
        int r_lo = row0 + wm * 32 + mt * 16 + g;
        int r_hi = r_lo + 8;
#pragma unroll
        for (int nt = 0; nt < 4; ++nt) {
            int col = wn * 32 + nt * 8 + 2 * c;
            if (r_lo < n_nodes)
                *(__half2*)(Yr + (size_t)r_lo * DFEAT + col) =
                    __floats2half2_rn(acc[mt][nt][0], acc[mt][nt][1]);
            if (r_hi < n_nodes)
                *(__half2*)(Yr + (size_t)r_hi * DFEAT + col) =
                    __floats2half2_rn(acc[mt][nt][2], acc[mt][nt][3]);
        }
    }
}

// ---------------------------------------------------------------------------
// CSR build
// ---------------------------------------------------------------------------
__global__ void zero_deg_k(int n)
{
    int i = blockIdx.x * blockDim.x + threadIdx.x;
    if (i < n) g_deg[i] = 0;
}

__global__ void hist_k(const int* __restrict__ dst, int E)
{
    int e = blockIdx.x * blockDim.x + threadIdx.x;
    if (e < E) atomicAdd(&g_deg[dst[e]], 1);
}

__global__ void scan1_k(int n)
{
    const int tid  = threadIdx.x;
    const int blk  = blockIdx.x;
    const int base = blk * SCAN_CHUNK + tid * 4;

    int d0 = 0, d1 = 0, d2 = 0, d3 = 0;
    if (base     < n) d0 = g_deg[base];
    if (base + 1 < n) d1 = g_deg[base + 1];
    if (base + 2 < n) d2 = g_deg[base + 2];
    if (base + 3 < n) d3 = g_deg[base + 3];
    int s = d0 + d1 + d2 + d3;

    const int lane = tid & 31, wid = tid >> 5;
    int v = s;
#pragma unroll
    for (int off = 1; off < 32; off <<= 1) {
        int t = __shfl_up_sync(0xffffffffu, v, off);
        if (lane >= off) v += t;
    }
    __shared__ int ws[8];
    if (lane == 31) ws[wid] = v;
    __syncthreads();
    if (tid == 0) {
        int r = 0;
#pragma unroll
        for (int i = 0; i < 8; ++i) { int t = ws[i]; ws[i] = r; r += t; }
    }
    __syncthreads();

    int excl = (v - s) + ws[wid];
    if (tid == 255) g_bsum[blk] = excl + s;

    if (base     < n) g_rowptr[base]     = excl;           excl += d0;
    if (base + 1 < n) g_rowptr[base + 1] = excl;           excl += d1;
    if (base + 2 < n) g_rowptr[base + 2] = excl;           excl += d2;
    if (base + 3 < n) g_rowptr[base + 3] = excl;
}

__global__ void scan2_k(int nb)
{
    const int lane = threadIdx.x;
    int i0 = lane * 2, i1 = lane * 2 + 1;
    int a = (i0 < nb) ? g_bsum[i0] : 0;
    int b = (i1 < nb) ? g_bsum[i1] : 0;
    int s = a + b, v = s;
#pragma unroll
    for (int off = 1; off < 32; off <<= 1) {
        int t = __shfl_up_sync(0xffffffffu, v, off);
        if (lane >= off) v += t;
    }
    int excl = v - s;
    if (i0 < nb) g_bsum[i0] = excl;
    if (i1 < nb) g_bsum[i1] = excl + a;
}

__global__ void scan3_k(int n, int E)
{
    const int tid  = threadIdx.x;
    const int blk  = blockIdx.x;
    const int off  = g_bsum[blk];
    const int base = blk * SCAN_CHUNK + tid * 4;
#pragma unroll
    for (int j = 0; j < 4; ++j) {
        int idx = base + j;
        if (idx < n) {
            int r = g_rowptr[idx] + off;
            g_rowptr[idx] = r;
            g_cursor[idx] = r;
        }
    }
    if (blk == 0 && tid == 0) g_rowptr[n] = E;
}

__global__ void scatter_k(const int* __restrict__ src, const int* __restrict__ dst,
                          const int* __restrict__ et, int E, int n)
{
    int e = blockIdx.x * blockDim.x + threadIdx.x;
    if (e >= E) return;
    int d   = dst[e];
    int pos = atomicAdd(&g_cursor[d], 1);
    g_elist[pos] = ((unsigned)et[e] * (unsigned)n + (unsigned)src[e]) * (unsigned)DFEAT;
}

// ---------------------------------------------------------------------------
// Pull: one warp per node. acc(fp32) = feat[n] + sum of fp16 Y rows.
// Per edge per lane: one 8B load. Unroll x8 for MLP.
// ---------------------------------------------------------------------------
__device__ __forceinline__ void acc_half4(float4& acc, uint2 u)
{
    float2 f0 = __half22float2(*(__half2*)&u.x);
    float2 f1 = __half22float2(*(__half2*)&u.y);
    acc.x += f0.x; acc.y += f0.y; acc.z += f1.x; acc.w += f1.y;
}

__global__ void __launch_bounds__(256)
pull_k(const float* __restrict__ feat, float* __restrict__ out, int n)
{
    int gw   = (blockIdx.x * 256 + threadIdx.x) >> 5;
    int lane = threadIdx.x & 31;
    if (gw >= n) return;

    int s = g_rowptr[gw];
    int e = g_rowptr[gw + 1];

    float4 acc = *((const float4*)feat + (size_t)gw * 32 + lane);
    const unsigned lo = (unsigned)lane * 4;   // half offset within row

    int i = s;
    for (; i + 8 <= e; i += 8) {
        uint2 u[8];
#pragma unroll
        for (int j = 0; j < 8; ++j) {
            unsigned o = g_elist[i + j];
            u[j] = *(const uint2*)(g_Y + (size_t)o + lo);
        }
#pragma unroll
        for (int j = 0; j < 8; ++j) acc_half4(acc, u[j]);
    }
    for (; i + 2 <= e; i += 2) {
        unsigned o0 = g_elist[i];
        unsigned o1 = g_elist[i + 1];
        uint2 u0 = *(const uint2*)(g_Y + (size_t)o0 + lo);
        uint2 u1 = *(const uint2*)(g_Y + (size_t)o1 + lo);
        acc_half4(acc, u0);
        acc_half4(acc, u1);
    }
    if (i < e) {
        unsigned o = g_elist[i];
        uint2 u = *(const uint2*)(g_Y + (size_t)o + lo);
        acc_half4(acc, u);
    }

    *((float4*)out + (size_t)gw * 32 + lane) = acc;
}

// ---------------------------------------------------------------------------
// Launch
// ---------------------------------------------------------------------------
extern "C" void kernel_launch(void* const* d_in, const int* in_sizes, int n_in,
                              void* d_out, int out_size)
{
    const float* feat = (const float*)d_in[0];
    const float* W    = (const float*)d_in[1];
    const int*   et   = (const int*)d_in[2];
    const int*   src  = (const int*)d_in[3];
    const int*   dst  = (const int*)d_in[4];
    float*       out  = (float*)d_out;

    const int n  = in_sizes[0] / DFEAT;                 // 50000
    const int R  = in_sizes[1] / (DFEAT * DFEAT);       // 8
    const int E  = in_sizes[2];                          // 640000
    const int nb = (n + SCAN_CHUNK - 1) / SCAN_CHUNK;    // 49

    dim3 tg(DFEAT / 32, DFEAT / 32, R);
    transpose_w<<<tg, dim3(32, 8)>>>(W);

    const int smem_bytes = (TM * HLD + DFEAT * HLD) * 2;  // ~52 KB
    cudaFuncSetAttribute(gemm_feat_w,
                         cudaFuncAttributeMaxDynamicSharedMemorySize, smem_bytes);

    dim3 gg((n + TM - 1) / TM, R);
    gemm_feat_w<<<gg, 256, smem_bytes>>>(feat, n);

    zero_deg_k<<<(n + 255) / 256, 256>>>(n);
    hist_k<<<(E + 255) / 256, 256>>>(dst, E);
    scan1_k<<<nb, 256>>>(n);
    scan2_k<<<1, 32>>>(nb);
    scan3_k<<<nb, 256>>>(n, E);
    scatter_k<<<(E + 255) / 256, 256>>>(src, dst, et, E, n);

    pull_k<<<(n * 32 + 255) / 256, 256>>>(feat, out, n);
}